// round 9
// baseline (speedup 1.0000x reference)
#include <cuda_runtime.h>
#include <cstdint>

#define NB 256
#define NT 512
#define NI 300
#define NH 128

typedef unsigned long long u64t;

// 64 MiB scratch for precomputed input projections xp[b][t][h]
__device__ float g_xp[NB * NT * NH];

// ---------------- packed f32x2 helpers (sm_103a) ----------------
__device__ __forceinline__ u64t pack2(float lo, float hi) {
    u64t r;
    asm("mov.b64 %0, {%1, %2};" : "=l"(r) : "f"(lo), "f"(hi));
    return r;
}
__device__ __forceinline__ void unpack2(u64t v, float& lo, float& hi) {
    asm("mov.b64 {%0, %1}, %2;" : "=f"(lo), "=f"(hi) : "l"(v));
}
__device__ __forceinline__ void ffma2(u64t& d, u64t a, u64t b) {
    asm("fma.rn.f32x2 %0, %1, %2, %0;" : "+l"(d) : "l"(a), "l"(b));
}
__device__ __forceinline__ void cp_async4(uint32_t s, const void* g) {
    asm volatile("cp.async.ca.shared.global [%0], [%1], 4;" :: "r"(s), "l"(g));
}
// fast tanh: 1 - 2/(e^{2x}+1) via MUFU ex2 + rcp (~1e-6 abs err; saturates
// correctly at +/-inf). 5 instrs vs ~40 for libm tanhf.
__device__ __forceinline__ float tanh_fast(float x) {
    float e;
    asm("ex2.approx.f32 %0, %1;" : "=f"(e) : "f"(x * 2.885390082f));  // 2*log2(e)
    float r;
    asm("rcp.approx.f32 %0, %1;" : "=f"(r) : "f"(e + 1.0f));
    return fmaf(-2.0f, r, 1.0f);
}

// ---------------------------------------------------------------------------
// Phase 1: xp = x @ W_ih^T + (b_ih + b_hh)
// BM=BN=128, BK=20. 256 threads, 8x8 micro-tile.
// W tile stored in SMEM PRE-DUPLICATED as {w,w} u64 pairs -> inner loop has
// zero pack MOVs: per kk = 2 LDS.128 (A pairs) + 4 LDS.128 (B dups) + 32 FFMA2.
// x streamed via cp.async double buffer; W register-staged (single ws buffer).
// ---------------------------------------------------------------------------
#define BM 128
#define BN 128
#define BK 20
#define BMP (BM + 4)
#define NTILES (NI / BK)

__global__ __launch_bounds__(256, 2) void gemm_xp_kernel(
    const float* __restrict__ x, const float* __restrict__ Wih,
    const float* __restrict__ bih, const float* __restrict__ bhh)
{
    __shared__ __align__(16) float xs[2][BK][BMP];     // 21120 B
    __shared__ __align__(16) u64t  ws2[BK][BN];        // 20480 B, {w,w} pairs
    __shared__ float bias_s[NH];

    const int tid = threadIdx.x;
    const int m0 = blockIdx.x * BM;
    if (tid < NH) bias_s[tid] = bih[tid] + bhh[tid];

    const int tr = tid >> 4;   // m rows tr*8 .. +7
    const int tc = tid & 15;   // n cols tc*8 .. +7

    // per-thread load map: idx = tid + it*256 -> (r, kk)
    uint32_t offSx[10];
    int offG[10], offWr[10], offWk[10];
#pragma unroll
    for (int it = 0; it < 10; it++) {
        int idx = tid + it * 256;
        int r = idx / BK, kk = idx % BK;
        offSx[it] = (uint32_t)(kk * BMP + r) * 4u;
        offG[it] = r * NI + kk;
        offWr[it] = r;
        offWk[it] = kk;
    }

    const uint32_t xsb0 = (uint32_t)__cvta_generic_to_shared(&xs[0][0][0]);
    const uint32_t xsb1 = (uint32_t)__cvta_generic_to_shared(&xs[1][0][0]);
    const float* xg = x + (long)m0 * NI;

    u64t acc2[4][8];   // [m-pair][n]
#pragma unroll
    for (int mp = 0; mp < 4; mp++)
#pragma unroll
        for (int n = 0; n < 8; n++) acc2[mp][n] = 0ull;

    // preload W tile 0 into regs; issue x tile 0
    float rw[10];
#pragma unroll
    for (int it = 0; it < 10; it++) rw[it] = Wih[offG[it]];
#pragma unroll
    for (int it = 0; it < 10; it++) cp_async4(xsb0 + offSx[it], xg + offG[it]);
    asm volatile("cp.async.commit_group;");

    for (int tile = 0; tile < NTILES; tile++) {
        int buf = tile & 1;

        // commit staged W (dup pairs) to smem; prev compute done (last barrier)
#pragma unroll
        for (int it = 0; it < 10; it++)
            ws2[offWk[it]][offWr[it]] = pack2(rw[it], rw[it]);

        asm volatile("cp.async.wait_group 0;");
        __syncthreads();   // ws2 + xs[buf] ready for everyone

        // stage next tile: W into regs, x via cp.async into other buffer
        if (tile + 1 < NTILES) {
            const float* wt_ = Wih + (tile + 1) * BK;
            const float* xt_ = xg + (tile + 1) * BK;
            uint32_t xsb = buf ? xsb0 : xsb1;
#pragma unroll
            for (int it = 0; it < 10; it++) {
                rw[it] = wt_[offG[it]];
                cp_async4(xsb + offSx[it], xt_ + offG[it]);
            }
            asm volatile("cp.async.commit_group;");
        }

        const float(*xsp)[BMP] = xs[buf];
#pragma unroll 4
        for (int kk = 0; kk < BK; kk++) {
            // A as 4 natural m-pairs (no packs)
            ulonglong2 aq0 = *(const ulonglong2*)&xsp[kk][tr * 8];
            ulonglong2 aq1 = *(const ulonglong2*)&xsp[kk][tr * 8 + 4];
            u64t ap[4] = {aq0.x, aq0.y, aq1.x, aq1.y};
            // B as 8 pre-duplicated {w,w} pairs (no packs)
            const u64t* wrow = &ws2[kk][tc * 8];
            ulonglong2 bq0 = *(const ulonglong2*)&wrow[0];
            ulonglong2 bq1 = *(const ulonglong2*)&wrow[2];
            ulonglong2 bq2 = *(const ulonglong2*)&wrow[4];
            ulonglong2 bq3 = *(const ulonglong2*)&wrow[6];
            u64t bp[8] = {bq0.x, bq0.y, bq1.x, bq1.y, bq2.x, bq2.y, bq3.x, bq3.y};
#pragma unroll
            for (int mp = 0; mp < 4; mp++)
#pragma unroll
                for (int n = 0; n < 8; n++)
                    ffma2(acc2[mp][n], ap[mp], bp[n]);
        }
        __syncthreads();   // protect ws2 / xs[buf] before next overwrite
    }

    // epilogue: unpack (lo = row 2mp, hi = row 2mp+1), add bias, store
#pragma unroll
    for (int mp = 0; mp < 4; mp++) {
        float lo[8], hi[8];
#pragma unroll
        for (int n = 0; n < 8; n++) {
            unpack2(acc2[mp][n], lo[n], hi[n]);
            lo[n] += bias_s[tc * 8 + n];
            hi[n] += bias_s[tc * 8 + n];
        }
        int r0 = m0 + tr * 8 + 2 * mp;
        float4* d0 = (float4*)&g_xp[(long)r0 * NH + tc * 8];
        float4* d1 = (float4*)&g_xp[(long)(r0 + 1) * NH + tc * 8];
        d0[0] = make_float4(lo[0], lo[1], lo[2], lo[3]);
        d0[1] = make_float4(lo[4], lo[5], lo[6], lo[7]);
        d1[0] = make_float4(hi[0], hi[1], hi[2], hi[3]);
        d1[1] = make_float4(hi[4], hi[5], hi[6], hi[7]);
    }
}

// ---------------------------------------------------------------------------
// Phase 2: scan. 128 CTAs x 256 threads, 2 batch rows/CTA.
// Thread (jg=tid>>3, row=(tid>>2)&1, ks=tid&3) computes 4 outputs
// j = jg*4..+3 of its row over strided k-slice {i*16 + ks*4 .. +3, i=0..7}.
//   - 64 FFMA2 + 8 LDS.128 per step (8:1 reuse), conflict-free broadcast
//   - quartet reduction: 2 stages, 3 SHFL, all-static value selects
//   - tanh via ex2/rcp approx (5 instrs)
// Lane ends owning output j = jg*4 + ks of its own row.
// ---------------------------------------------------------------------------
#define HSTRIDE 144   // row1 banks ≡ row0 banks + 16 -> disjoint halves

__global__ __launch_bounds__(256, 1) void rnn_scan_kernel(
    const float* __restrict__ Whh, const float* __restrict__ fcw,
    const float* __restrict__ fcb, float* __restrict__ out)
{
    __shared__ __align__(16) float hbuf[2][2][HSTRIDE];

    const int tid = threadIdx.x;
    const int ks = tid & 3;
    const int row = (tid >> 2) & 1;
    const int jg = tid >> 3;        // 0..31
    const int j0 = jg * 4;
    const int jmine = j0 + ks;
    const int b0 = blockIdx.x * 2;

    // weights: w2[jl][2i+c] covers k = i*16 + ks*4 + 2c (+1)
    u64t w2[4][16];
#pragma unroll
    for (int jl = 0; jl < 4; jl++) {
        const ulonglong2* wp = (const ulonglong2*)(Whh + (j0 + jl) * NH);
#pragma unroll
        for (int i = 0; i < 8; i++) {
            ulonglong2 v = wp[i * 4 + ks];
            w2[jl][2 * i] = v.x;
            w2[jl][2 * i + 1] = v.y;
        }
    }

    hbuf[0][tid & 1][tid >> 1] = 0.f;
    __syncthreads();

    const float* __restrict__ xq = g_xp + (long)(b0 + row) * (NT * NH);
    float nxa = xq[jmine];
    float nxb = xq[NH + jmine];

    const bool k2 = (ks & 2) != 0;
    const bool k1 = (ks & 1) != 0;

    int cur = 0;
    for (int t = 0; t < NT; t++) {
        float xv = nxa;
        nxa = nxb;
        if (t + 2 < NT) nxb = xq[(t + 2) * NH + jmine];

        const float* hrow = &hbuf[cur][row][0];
        u64t c0 = 0ull, c1 = 0ull, c2 = 0ull, c3 = 0ull;
#pragma unroll
        for (int i = 0; i < 8; i++) {
            ulonglong2 p = *(const ulonglong2*)(hrow + i * 16 + ks * 4);
            ffma2(c0, p.x, w2[0][2 * i]);
            ffma2(c1, p.x, w2[1][2 * i]);
            ffma2(c2, p.x, w2[2][2 * i]);
            ffma2(c3, p.x, w2[3][2 * i]);
            ffma2(c0, p.y, w2[0][2 * i + 1]);
            ffma2(c1, p.y, w2[1][2 * i + 1]);
            ffma2(c2, p.y, w2[2][2 * i + 1]);
            ffma2(c3, p.y, w2[3][2 * i + 1]);
        }

        float lo, hi;
        unpack2(c0, lo, hi); float s0 = lo + hi;
        unpack2(c1, lo, hi); float s1 = lo + hi;
        unpack2(c2, lo, hi); float s2 = lo + hi;
        unpack2(c3, lo, hi); float s3 = lo + hi;

        // stage 1 (xor 2): combine k-slices {0,2} and {1,3}
        float send0 = k2 ? s0 : s2;
        float send1 = k2 ? s1 : s3;
        float keep0 = k2 ? s2 : s0;
        float keep1 = k2 ? s3 : s1;
        float u0 = keep0 + __shfl_xor_sync(0xffffffffu, send0, 2);
        float u1 = keep1 + __shfl_xor_sync(0xffffffffu, send1, 2);
        // stage 2 (xor 1): full sums; lane ks keeps output j0+ks
        float sd = k1 ? u0 : u1;
        float kp = k1 ? u1 : u0;
        float tot = kp + __shfl_xor_sync(0xffffffffu, sd, 1);

        int nxt = cur ^ 1;
        hbuf[nxt][row][jmine] = tanh_fast(tot + xv);
        __syncthreads();
        cur = nxt;
    }

    // fused FC (128 -> 2)
    if (tid < 128) {
        const int w = tid >> 5, lane = tid & 31;
        const int frow = w >> 1, cls = w & 1;
        const float* h = &hbuf[cur][frow][0];
        float s = 0.f;
#pragma unroll
        for (int kk = 0; kk < NH; kk += 32)
            s += h[kk + lane] * fcw[cls * NH + kk + lane];
#pragma unroll
        for (int off = 16; off > 0; off >>= 1)
            s += __shfl_xor_sync(0xffffffffu, s, off);
        if (lane == 0) out[(b0 + frow) * 2 + cls] = s + fcb[cls];
    }
}

// ---------------------------------------------------------------------------
extern "C" void kernel_launch(void* const* d_in, const int* in_sizes, int n_in,
                              void* d_out, int out_size)
{
    const float* x   = (const float*)d_in[0];
    const float* Wih = (const float*)d_in[1];
    const float* Whh = (const float*)d_in[2];
    const float* bih = (const float*)d_in[3];
    const float* bhh = (const float*)d_in[4];
    const float* fcw = (const float*)d_in[5];
    const float* fcb = (const float*)d_in[6];
    float* out = (float*)d_out;

    (void)in_sizes; (void)n_in; (void)out_size;

    gemm_xp_kernel<<<(NB * NT) / BM, 256>>>(x, Wih, bih, bhh);
    rnn_scan_kernel<<<NB / 2, 256>>>(Whh, fcw, fcb, out);
}

// round 11
// speedup vs baseline: 1.6235x; 1.6235x over previous
#include <cuda_runtime.h>
#include <cstdint>

#define NB 256
#define NT 512
#define NI 300
#define NH 128

typedef unsigned long long u64t;

// 64 MiB scratch for precomputed input projections xp[b][t][h]
__device__ float g_xp[NB * NT * NH];

// ---------------- packed f32x2 helpers (sm_103a) ----------------
__device__ __forceinline__ u64t pack2(float lo, float hi) {
    u64t r;
    asm("mov.b64 %0, {%1, %2};" : "=l"(r) : "f"(lo), "f"(hi));
    return r;
}
__device__ __forceinline__ void unpack2(u64t v, float& lo, float& hi) {
    asm("mov.b64 {%0, %1}, %2;" : "=f"(lo), "=f"(hi) : "l"(v));
}
__device__ __forceinline__ void ffma2(u64t& d, u64t a, u64t b) {
    asm("fma.rn.f32x2 %0, %1, %2, %0;" : "+l"(d) : "l"(a), "l"(b));
}
__device__ __forceinline__ void cp_async4(uint32_t s, const void* g) {
    asm volatile("cp.async.ca.shared.global [%0], [%1], 4;" :: "r"(s), "l"(g));
}
// fast tanh: 1 - 2/(e^{2x}+1) via MUFU ex2 + rcp (~1e-6 abs err)
__device__ __forceinline__ float tanh_fast(float x) {
    float e;
    asm("ex2.approx.f32 %0, %1;" : "=f"(e) : "f"(x * 2.885390082f));  // 2*log2(e)
    float r;
    asm("rcp.approx.f32 %0, %1;" : "=f"(r) : "f"(e + 1.0f));
    return fmaf(-2.0f, r, 1.0f);
}

// ---------------------------------------------------------------------------
// Phase 1: xp = x @ W_ih^T + (b_ih + b_hh)   — ROUND-6 VERSION (known good)
// ---------------------------------------------------------------------------
#define BM 128
#define BN 128
#define BK 20
#define BMP (BM + 4)
#define NTILES (NI / BK)

__global__ __launch_bounds__(256, 2) void gemm_xp_kernel(
    const float* __restrict__ x, const float* __restrict__ Wih,
    const float* __restrict__ bih, const float* __restrict__ bhh)
{
    __shared__ __align__(16) float xs[2][BK][BMP];
    __shared__ __align__(16) float ws[2][BK][BMP];
    __shared__ float bias_s[NH];

    const int tid = threadIdx.x;
    const int m0 = blockIdx.x * BM;
    if (tid < NH) bias_s[tid] = bih[tid] + bhh[tid];

    const int tr = tid >> 4;
    const int tc = tid & 15;

    uint32_t offS[10];
    int offG[10];
#pragma unroll
    for (int it = 0; it < 10; it++) {
        int idx = tid + it * 256;
        int r = idx / BK, kk = idx % BK;
        offS[it] = (uint32_t)(kk * BMP + r) * 4u;
        offG[it] = r * NI + kk;
    }

    const uint32_t xsb0 = (uint32_t)__cvta_generic_to_shared(&xs[0][0][0]);
    const uint32_t xsb1 = (uint32_t)__cvta_generic_to_shared(&xs[1][0][0]);
    const uint32_t wsb0 = (uint32_t)__cvta_generic_to_shared(&ws[0][0][0]);
    const uint32_t wsb1 = (uint32_t)__cvta_generic_to_shared(&ws[1][0][0]);

    const float* xg = x + (long)m0 * NI;

    u64t acc2[8][4];
#pragma unroll
    for (int i = 0; i < 8; i++)
#pragma unroll
        for (int p = 0; p < 4; p++) acc2[i][p] = 0ull;

#define ISSUE_TILE(tile, xsb, wsb)                                   \
    do {                                                             \
        const float* xt_ = xg + (tile) * BK;                         \
        const float* wt_ = Wih + (tile) * BK;                        \
        _Pragma("unroll")                                            \
        for (int it = 0; it < 10; it++) {                            \
            cp_async4((xsb) + offS[it], xt_ + offG[it]);             \
            cp_async4((wsb) + offS[it], wt_ + offG[it]);             \
        }                                                            \
        asm volatile("cp.async.commit_group;");                      \
    } while (0)

    ISSUE_TILE(0, xsb0, wsb0);

    for (int tile = 0; tile < NTILES; tile++) {
        int buf = tile & 1;
        if (tile + 1 < NTILES) {
            if (buf == 0) ISSUE_TILE(tile + 1, xsb1, wsb1);
            else          ISSUE_TILE(tile + 1, xsb0, wsb0);
            asm volatile("cp.async.wait_group 1;");
        } else {
            asm volatile("cp.async.wait_group 0;");
        }
        __syncthreads();

        const float(*xsp)[BMP] = xs[buf];
        const float(*wsp)[BMP] = ws[buf];
#pragma unroll 4
        for (int kk = 0; kk < BK; kk++) {
            float4 a0 = *(const float4*)&xsp[kk][tr * 8];
            float4 a1 = *(const float4*)&xsp[kk][tr * 8 + 4];
            ulonglong2 bq0 = *(const ulonglong2*)&wsp[kk][tc * 8];
            ulonglong2 bq1 = *(const ulonglong2*)&wsp[kk][tc * 8 + 4];
            u64t bp[4] = {bq0.x, bq0.y, bq1.x, bq1.y};
            float av[8] = {a0.x, a0.y, a0.z, a0.w, a1.x, a1.y, a1.z, a1.w};
#pragma unroll
            for (int i = 0; i < 8; i++) {
                u64t ap = pack2(av[i], av[i]);
#pragma unroll
                for (int p = 0; p < 4; p++)
                    ffma2(acc2[i][p], ap, bp[p]);
            }
        }
        __syncthreads();
    }
#undef ISSUE_TILE

#pragma unroll
    for (int i = 0; i < 8; i++) {
        int r = m0 + tr * 8 + i;
        float* pdst = &g_xp[r * NH + tc * 8];
#pragma unroll
        for (int p = 0; p < 4; p++) {
            float lo, hi;
            unpack2(acc2[i][p], lo, hi);
            float2 v;
            v.x = lo + bias_s[tc * 8 + 2 * p];
            v.y = hi + bias_s[tc * 8 + 2 * p + 1];
            *(float2*)(pdst + 2 * p) = v;
        }
    }
}

// ---------------------------------------------------------------------------
// Phase 2: scan. 128 CTAs x 512 threads (4 warps/SMSP), 2 batch rows/CTA.
// Thread (jg=tid>>4, row=(tid>>3)&1, ks=tid&7) computes 4 outputs
// j = jg*4..+3 of its row over strided k-slice {i*32 + ks*4 .. +3, i=0..3}.
//   - 32 FFMA2 + 4 LDS.128 per step (8:1 reuse), conflict-free
//   - octet reduction: THREE xor-stages (4 SHFL total). Stages 4 and 2
//     narrow 4 values -> 1 per lane (with value selects); after them lane
//     (k4,k2,k1) holds output j0+2*k4+k2 summed over HALF the slices
//     (k1-even or k1-odd sets) -> final xor-1 stage (no select) completes
//     the sum. This was the round-10 bug: the halves are complementary,
//     not duplicates.
//   - tanh via ex2/rcp (5 instrs); k1==0 lane writes.
// ---------------------------------------------------------------------------
#define HSTRIDE 136

__global__ __launch_bounds__(512, 1) void rnn_scan_kernel(
    const float* __restrict__ Whh, const float* __restrict__ fcw,
    const float* __restrict__ fcb, float* __restrict__ out)
{
    __shared__ __align__(16) float hbuf[2][2][HSTRIDE];

    const int tid = threadIdx.x;
    const int ks = tid & 7;
    const int row = (tid >> 3) & 1;
    const int jg = tid >> 4;        // 0..31
    const int j0 = jg * 4;
    const int b0 = blockIdx.x * 2;

    const int k4 = (ks >> 2) & 1;
    const int k2 = (ks >> 1) & 1;
    const int k1 = ks & 1;
    const int jmine = j0 + 2 * k4 + k2;   // output this lane owns post-reduce

    // weights: w2[jl][2i+c] = {W[j0+jl][i*32+ks*4+2c], ...+2c+1}, i=0..3
    u64t w2[4][8];
#pragma unroll
    for (int jl = 0; jl < 4; jl++) {
        const ulonglong2* wp = (const ulonglong2*)(Whh + (j0 + jl) * NH);
#pragma unroll
        for (int i = 0; i < 4; i++) {
            ulonglong2 v = wp[i * 8 + ks];
            w2[jl][2 * i] = v.x;
            w2[jl][2 * i + 1] = v.y;
        }
    }

    if (tid < 256) hbuf[0][tid & 1][tid >> 1] = 0.f;
    __syncthreads();

    const float* __restrict__ xq = g_xp + (long)(b0 + row) * (NT * NH);
    float nxa = xq[jmine];
    float nxb = xq[NH + jmine];

    int cur = 0;
    for (int t = 0; t < NT; t++) {
        float xv = nxa;
        nxa = nxb;
        if (t + 2 < NT) nxb = xq[(t + 2) * NH + jmine];

        const float* hrow = &hbuf[cur][row][0];
        u64t c0 = 0ull, c1 = 0ull, c2 = 0ull, c3 = 0ull;
#pragma unroll
        for (int i = 0; i < 4; i++) {
            ulonglong2 p = *(const ulonglong2*)(hrow + i * 32 + ks * 4);
            ffma2(c0, p.x, w2[0][2 * i]);
            ffma2(c1, p.x, w2[1][2 * i]);
            ffma2(c2, p.x, w2[2][2 * i]);
            ffma2(c3, p.x, w2[3][2 * i]);
            ffma2(c0, p.y, w2[0][2 * i + 1]);
            ffma2(c1, p.y, w2[1][2 * i + 1]);
            ffma2(c2, p.y, w2[2][2 * i + 1]);
            ffma2(c3, p.y, w2[3][2 * i + 1]);
        }

        float lo, hi;
        unpack2(c0, lo, hi); float s0 = lo + hi;
        unpack2(c1, lo, hi); float s1 = lo + hi;
        unpack2(c2, lo, hi); float s2 = lo + hi;
        unpack2(c3, lo, hi); float s3 = lo + hi;

        // stage 1 (xor 4): keep outputs {2*k4, 2*k4+1}
        float send0 = k4 ? s0 : s2;
        float send1 = k4 ? s1 : s3;
        float keep0 = k4 ? s2 : s0;
        float keep1 = k4 ? s3 : s1;
        float u0 = keep0 + __shfl_xor_sync(0xffffffffu, send0, 4);
        float u1 = keep1 + __shfl_xor_sync(0xffffffffu, send1, 4);
        // stage 2 (xor 2): keep output 2*k4 + k2 (summed over k1-parity slices)
        float sd = k2 ? u0 : u1;
        float kp = k2 ? u1 : u0;
        float half_tot = kp + __shfl_xor_sync(0xffffffffu, sd, 2);
        // stage 3 (xor 1): merge complementary slice halves -> full sum
        float tot = half_tot + __shfl_xor_sync(0xffffffffu, half_tot, 1);

        int nxt = cur ^ 1;
        if (k1 == 0) hbuf[nxt][row][jmine] = tanh_fast(tot + xv);
        __syncthreads();
        cur = nxt;
    }

    // fused FC (128 -> 2)
    if (tid < 128) {
        const int w = tid >> 5, lane = tid & 31;
        const int frow = w >> 1, cls = w & 1;
        const float* h = &hbuf[cur][frow][0];
        float s = 0.f;
#pragma unroll
        for (int kk = 0; kk < NH; kk += 32)
            s += h[kk + lane] * fcw[cls * NH + kk + lane];
#pragma unroll
        for (int off = 16; off > 0; off >>= 1)
            s += __shfl_xor_sync(0xffffffffu, s, off);
        if (lane == 0) out[(b0 + frow) * 2 + cls] = s + fcb[cls];
    }
}

// ---------------------------------------------------------------------------
extern "C" void kernel_launch(void* const* d_in, const int* in_sizes, int n_in,
                              void* d_out, int out_size)
{
    const float* x   = (const float*)d_in[0];
    const float* Wih = (const float*)d_in[1];
    const float* Whh = (const float*)d_in[2];
    const float* bih = (const float*)d_in[3];
    const float* bhh = (const float*)d_in[4];
    const float* fcw = (const float*)d_in[5];
    const float* fcb = (const float*)d_in[6];
    float* out = (float*)d_out;

    (void)in_sizes; (void)n_in; (void)out_size;

    gemm_xp_kernel<<<(NB * NT) / BM, 256>>>(x, Wih, bih, bhh);
    rnn_scan_kernel<<<NB / 2, 512>>>(Whh, fcw, fcb, out);
}

// round 12
// speedup vs baseline: 1.7357x; 1.0691x over previous
#include <cuda_runtime.h>
#include <cstdint>

#define NB 256
#define NT 512
#define NI 300
#define NH 128

typedef unsigned long long u64t;

// 64 MiB scratch for precomputed input projections xp[b][t][h]
__device__ float g_xp[NB * NT * NH];

// ---------------- packed f32x2 helpers (sm_103a) ----------------
__device__ __forceinline__ u64t pack2(float lo, float hi) {
    u64t r;
    asm("mov.b64 %0, {%1, %2};" : "=l"(r) : "f"(lo), "f"(hi));
    return r;
}
__device__ __forceinline__ void unpack2(u64t v, float& lo, float& hi) {
    asm("mov.b64 {%0, %1}, %2;" : "=f"(lo), "=f"(hi) : "l"(v));
}
__device__ __forceinline__ void ffma2(u64t& d, u64t a, u64t b) {
    asm("fma.rn.f32x2 %0, %1, %2, %0;" : "+l"(d) : "l"(a), "l"(b));
}
__device__ __forceinline__ void cp_async4(uint32_t s, const void* g) {
    asm volatile("cp.async.ca.shared.global [%0], [%1], 4;" :: "r"(s), "l"(g));
}
// fast tanh: 1 - 2/(e^{2x}+1) via MUFU ex2 + rcp (~1e-6 abs err)
__device__ __forceinline__ float tanh_fast(float x) {
    float e;
    asm("ex2.approx.f32 %0, %1;" : "=f"(e) : "f"(x * 2.885390082f));  // 2*log2(e)
    float r;
    asm("rcp.approx.f32 %0, %1;" : "=f"(r) : "f"(e + 1.0f));
    return fmaf(-2.0f, r, 1.0f);
}

// ---------------------------------------------------------------------------
// Phase 1: xp = x @ W_ih^T + (b_ih + b_hh)   — ROUND-6 VERSION (known good)
// ---------------------------------------------------------------------------
#define BM 128
#define BN 128
#define BK 20
#define BMP (BM + 4)
#define NTILES (NI / BK)

__global__ __launch_bounds__(256, 2) void gemm_xp_kernel(
    const float* __restrict__ x, const float* __restrict__ Wih,
    const float* __restrict__ bih, const float* __restrict__ bhh)
{
    __shared__ __align__(16) float xs[2][BK][BMP];
    __shared__ __align__(16) float ws[2][BK][BMP];
    __shared__ float bias_s[NH];

    const int tid = threadIdx.x;
    const int m0 = blockIdx.x * BM;
    if (tid < NH) bias_s[tid] = bih[tid] + bhh[tid];

    const int tr = tid >> 4;
    const int tc = tid & 15;

    uint32_t offS[10];
    int offG[10];
#pragma unroll
    for (int it = 0; it < 10; it++) {
        int idx = tid + it * 256;
        int r = idx / BK, kk = idx % BK;
        offS[it] = (uint32_t)(kk * BMP + r) * 4u;
        offG[it] = r * NI + kk;
    }

    const uint32_t xsb0 = (uint32_t)__cvta_generic_to_shared(&xs[0][0][0]);
    const uint32_t xsb1 = (uint32_t)__cvta_generic_to_shared(&xs[1][0][0]);
    const uint32_t wsb0 = (uint32_t)__cvta_generic_to_shared(&ws[0][0][0]);
    const uint32_t wsb1 = (uint32_t)__cvta_generic_to_shared(&ws[1][0][0]);

    const float* xg = x + (long)m0 * NI;

    u64t acc2[8][4];
#pragma unroll
    for (int i = 0; i < 8; i++)
#pragma unroll
        for (int p = 0; p < 4; p++) acc2[i][p] = 0ull;

#define ISSUE_TILE(tile, xsb, wsb)                                   \
    do {                                                             \
        const float* xt_ = xg + (tile) * BK;                         \
        const float* wt_ = Wih + (tile) * BK;                        \
        _Pragma("unroll")                                            \
        for (int it = 0; it < 10; it++) {                            \
            cp_async4((xsb) + offS[it], xt_ + offG[it]);             \
            cp_async4((wsb) + offS[it], wt_ + offG[it]);             \
        }                                                            \
        asm volatile("cp.async.commit_group;");                      \
    } while (0)

    ISSUE_TILE(0, xsb0, wsb0);

    for (int tile = 0; tile < NTILES; tile++) {
        int buf = tile & 1;
        if (tile + 1 < NTILES) {
            if (buf == 0) ISSUE_TILE(tile + 1, xsb1, wsb1);
            else          ISSUE_TILE(tile + 1, xsb0, wsb0);
            asm volatile("cp.async.wait_group 1;");
        } else {
            asm volatile("cp.async.wait_group 0;");
        }
        __syncthreads();

        const float(*xsp)[BMP] = xs[buf];
        const float(*wsp)[BMP] = ws[buf];
#pragma unroll 4
        for (int kk = 0; kk < BK; kk++) {
            float4 a0 = *(const float4*)&xsp[kk][tr * 8];
            float4 a1 = *(const float4*)&xsp[kk][tr * 8 + 4];
            ulonglong2 bq0 = *(const ulonglong2*)&wsp[kk][tc * 8];
            ulonglong2 bq1 = *(const ulonglong2*)&wsp[kk][tc * 8 + 4];
            u64t bp[4] = {bq0.x, bq0.y, bq1.x, bq1.y};
            float av[8] = {a0.x, a0.y, a0.z, a0.w, a1.x, a1.y, a1.z, a1.w};
#pragma unroll
            for (int i = 0; i < 8; i++) {
                u64t ap = pack2(av[i], av[i]);
#pragma unroll
                for (int p = 0; p < 4; p++)
                    ffma2(acc2[i][p], ap, bp[p]);
            }
        }
        __syncthreads();
    }
#undef ISSUE_TILE

#pragma unroll
    for (int i = 0; i < 8; i++) {
        int r = m0 + tr * 8 + i;
        float* pdst = &g_xp[r * NH + tc * 8];
#pragma unroll
        for (int p = 0; p < 4; p++) {
            float lo, hi;
            unpack2(acc2[i][p], lo, hi);
            float2 v;
            v.x = lo + bias_s[tc * 8 + 2 * p];
            v.y = hi + bias_s[tc * 8 + 2 * p + 1];
            *(float2*)(pdst + 2 * p) = v;
        }
    }
}

// ---------------------------------------------------------------------------
// Phase 2: scan, ONE batch row per CTA, 256 CTAs x 256 threads,
// TWO CTAs co-resident per SM (phase-independent barrier groups -> while one
// CTA sits in its per-step serial path / barrier, the other's warps issue).
// Thread (j = tid>>1, half = tid&1) computes the half-dot (64 k's) of
// output j: 32 FFMA2 + 4 broadcast LDS.128, weights in 64 regs.
// One shfl_xor(1) combines halves; half==0 lane applies tanh and writes.
// ---------------------------------------------------------------------------
__global__ __launch_bounds__(256, 2) void rnn_scan_kernel(
    const float* __restrict__ Whh, const float* __restrict__ fcw,
    const float* __restrict__ fcb, float* __restrict__ out)
{
    __shared__ __align__(16) float hbuf[2][NH];

    const int tid = threadIdx.x;
    const int j = tid >> 1;
    const int half = tid & 1;
    const int b = blockIdx.x;          // one batch row per CTA

    // weights: 64 contiguous floats W[j][half*64 .. +63] as 32 packed pairs
    u64t w2[32];
    {
        const ulonglong2* wp = (const ulonglong2*)(Whh + j * NH + half * 64);
#pragma unroll
        for (int i = 0; i < 16; i++) {
            ulonglong2 v = wp[i];
            w2[2 * i] = v.x;
            w2[2 * i + 1] = v.y;
        }
    }

    if (tid < NH) hbuf[0][tid] = 0.f;
    __syncthreads();

    const float* __restrict__ xq = g_xp + (long)b * (NT * NH);
    // prefetch depth 3 (cheap; generous cover for the DRAM stream)
    float nxa = xq[j];
    float nxb = xq[NH + j];
    float nxc = xq[2 * NH + j];

    int cur = 0;
    for (int t = 0; t < NT; t++) {
        float xv = nxa;
        nxa = nxb; nxb = nxc;
        if (t + 3 < NT) nxc = xq[(t + 3) * NH + j];

        const float* hs = &hbuf[cur][half * 64];
        // two packed accumulator chains
        u64t ca = 0ull, cb = 0ull;
#pragma unroll
        for (int i = 0; i < 4; i++) {
            ulonglong2 p = *(const ulonglong2*)(hs + i * 16);
            ulonglong2 q = *(const ulonglong2*)(hs + i * 16 + 4);
            ulonglong2 r = *(const ulonglong2*)(hs + i * 16 + 8);
            ulonglong2 s = *(const ulonglong2*)(hs + i * 16 + 12);
            ffma2(ca, p.x, w2[i * 8 + 0]);
            ffma2(cb, p.y, w2[i * 8 + 1]);
            ffma2(ca, q.x, w2[i * 8 + 2]);
            ffma2(cb, q.y, w2[i * 8 + 3]);
            ffma2(ca, r.x, w2[i * 8 + 4]);
            ffma2(cb, r.y, w2[i * 8 + 5]);
            ffma2(ca, s.x, w2[i * 8 + 6]);
            ffma2(cb, s.y, w2[i * 8 + 7]);
        }

        float lo, hi;
        unpack2(ca, lo, hi); float sum = lo + hi;
        unpack2(cb, lo, hi); sum += lo + hi;

        // combine the two half-dots (partner = adjacent lane)
        float tot = sum + __shfl_xor_sync(0xffffffffu, sum, 1);

        int nxt = cur ^ 1;
        if (half == 0) hbuf[nxt][j] = tanh_fast(tot + xv);
        __syncthreads();
        cur = nxt;
    }

    // fused FC (128 -> 2): warp 0 -> class 0, warp 1 -> class 1
    if (tid < 64) {
        const int w = tid >> 5, lane = tid & 31;
        const float* h = &hbuf[cur][0];
        float s = 0.f;
#pragma unroll
        for (int kk = 0; kk < NH; kk += 32)
            s += h[kk + lane] * fcw[w * NH + kk + lane];
#pragma unroll
        for (int off = 16; off > 0; off >>= 1)
            s += __shfl_xor_sync(0xffffffffu, s, off);
        if (lane == 0) out[b * 2 + w] = s + fcb[w];
    }
}

// ---------------------------------------------------------------------------
extern "C" void kernel_launch(void* const* d_in, const int* in_sizes, int n_in,
                              void* d_out, int out_size)
{
    const float* x   = (const float*)d_in[0];
    const float* Wih = (const float*)d_in[1];
    const float* Whh = (const float*)d_in[2];
    const float* bih = (const float*)d_in[3];
    const float* bhh = (const float*)d_in[4];
    const float* fcw = (const float*)d_in[5];
    const float* fcb = (const float*)d_in[6];
    float* out = (float*)d_out;

    (void)in_sizes; (void)n_in; (void)out_size;

    gemm_xp_kernel<<<(NB * NT) / BM, 256>>>(x, Wih, bih, bhh);
    rnn_scan_kernel<<<NB, 256>>>(Whh, fcw, fcb, out);
}

// round 13
// speedup vs baseline: 1.7843x; 1.0280x over previous
#include <cuda_runtime.h>
#include <cstdint>

#define NB 256
#define NT 512
#define NI 300
#define NH 128

typedef unsigned long long u64t;

// Precomputed input projections xp[b][t][h], padded by 8 timesteps so the
// distance-4 register prefetch in the scan can overrun harmlessly.
__device__ float g_xp[(NB * NT + 8) * NH];

// ---------------- packed f32x2 helpers (sm_103a) ----------------
__device__ __forceinline__ u64t pack2(float lo, float hi) {
    u64t r;
    asm("mov.b64 %0, {%1, %2};" : "=l"(r) : "f"(lo), "f"(hi));
    return r;
}
__device__ __forceinline__ void unpack2(u64t v, float& lo, float& hi) {
    asm("mov.b64 {%0, %1}, %2;" : "=f"(lo), "=f"(hi) : "l"(v));
}
__device__ __forceinline__ void ffma2(u64t& d, u64t a, u64t b) {
    asm("fma.rn.f32x2 %0, %1, %2, %0;" : "+l"(d) : "l"(a), "l"(b));
}
__device__ __forceinline__ void cp_async4(uint32_t s, const void* g) {
    asm volatile("cp.async.ca.shared.global [%0], [%1], 4;" :: "r"(s), "l"(g));
}
// fast tanh: 1 - 2/(e^{2x}+1) via MUFU ex2 + rcp (~1e-6 abs err)
__device__ __forceinline__ float tanh_fast(float x) {
    float e;
    asm("ex2.approx.f32 %0, %1;" : "=f"(e) : "f"(x * 2.885390082f));  // 2*log2(e)
    float r;
    asm("rcp.approx.f32 %0, %1;" : "=f"(r) : "f"(e + 1.0f));
    return fmaf(-2.0f, r, 1.0f);
}

// ---------------------------------------------------------------------------
// Phase 1: xp = x @ W_ih^T + (b_ih + b_hh)   — ROUND-6 VERSION (known good)
// ---------------------------------------------------------------------------
#define BM 128
#define BN 128
#define BK 20
#define BMP (BM + 4)
#define NTILES (NI / BK)

__global__ __launch_bounds__(256, 2) void gemm_xp_kernel(
    const float* __restrict__ x, const float* __restrict__ Wih,
    const float* __restrict__ bih, const float* __restrict__ bhh)
{
    __shared__ __align__(16) float xs[2][BK][BMP];
    __shared__ __align__(16) float ws[2][BK][BMP];
    __shared__ float bias_s[NH];

    const int tid = threadIdx.x;
    const int m0 = blockIdx.x * BM;
    if (tid < NH) bias_s[tid] = bih[tid] + bhh[tid];

    const int tr = tid >> 4;
    const int tc = tid & 15;

    uint32_t offS[10];
    int offG[10];
#pragma unroll
    for (int it = 0; it < 10; it++) {
        int idx = tid + it * 256;
        int r = idx / BK, kk = idx % BK;
        offS[it] = (uint32_t)(kk * BMP + r) * 4u;
        offG[it] = r * NI + kk;
    }

    const uint32_t xsb0 = (uint32_t)__cvta_generic_to_shared(&xs[0][0][0]);
    const uint32_t xsb1 = (uint32_t)__cvta_generic_to_shared(&xs[1][0][0]);
    const uint32_t wsb0 = (uint32_t)__cvta_generic_to_shared(&ws[0][0][0]);
    const uint32_t wsb1 = (uint32_t)__cvta_generic_to_shared(&ws[1][0][0]);

    const float* xg = x + (long)m0 * NI;

    u64t acc2[8][4];
#pragma unroll
    for (int i = 0; i < 8; i++)
#pragma unroll
        for (int p = 0; p < 4; p++) acc2[i][p] = 0ull;

#define ISSUE_TILE(tile, xsb, wsb)                                   \
    do {                                                             \
        const float* xt_ = xg + (tile) * BK;                         \
        const float* wt_ = Wih + (tile) * BK;                        \
        _Pragma("unroll")                                            \
        for (int it = 0; it < 10; it++) {                            \
            cp_async4((xsb) + offS[it], xt_ + offG[it]);             \
            cp_async4((wsb) + offS[it], wt_ + offG[it]);             \
        }                                                            \
        asm volatile("cp.async.commit_group;");                      \
    } while (0)

    ISSUE_TILE(0, xsb0, wsb0);

    for (int tile = 0; tile < NTILES; tile++) {
        int buf = tile & 1;
        if (tile + 1 < NTILES) {
            if (buf == 0) ISSUE_TILE(tile + 1, xsb1, wsb1);
            else          ISSUE_TILE(tile + 1, xsb0, wsb0);
            asm volatile("cp.async.wait_group 1;");
        } else {
            asm volatile("cp.async.wait_group 0;");
        }
        __syncthreads();

        const float(*xsp)[BMP] = xs[buf];
        const float(*wsp)[BMP] = ws[buf];
#pragma unroll 4
        for (int kk = 0; kk < BK; kk++) {
            float4 a0 = *(const float4*)&xsp[kk][tr * 8];
            float4 a1 = *(const float4*)&xsp[kk][tr * 8 + 4];
            ulonglong2 bq0 = *(const ulonglong2*)&wsp[kk][tc * 8];
            ulonglong2 bq1 = *(const ulonglong2*)&wsp[kk][tc * 8 + 4];
            u64t bp[4] = {bq0.x, bq0.y, bq1.x, bq1.y};
            float av[8] = {a0.x, a0.y, a0.z, a0.w, a1.x, a1.y, a1.z, a1.w};
#pragma unroll
            for (int i = 0; i < 8; i++) {
                u64t ap = pack2(av[i], av[i]);
#pragma unroll
                for (int p = 0; p < 4; p++)
                    ffma2(acc2[i][p], ap, bp[p]);
            }
        }
        __syncthreads();
    }
#undef ISSUE_TILE

#pragma unroll
    for (int i = 0; i < 8; i++) {
        int r = m0 + tr * 8 + i;
        float* pdst = &g_xp[r * NH + tc * 8];
#pragma unroll
        for (int p = 0; p < 4; p++) {
            float lo, hi;
            unpack2(acc2[i][p], lo, hi);
            float2 v;
            v.x = lo + bias_s[tc * 8 + 2 * p];
            v.y = hi + bias_s[tc * 8 + 2 * p + 1];
            *(float2*)(pdst + 2 * p) = v;
        }
    }
}

// ---------------------------------------------------------------------------
// Phase 2: scan, ONE batch row per CTA, 256 CTAs x 256 threads.
// Thread (j = tid>>1, half = tid&1) computes the half-dot (64 k's) of output
// j; one shfl_xor(1) combines halves; half==0 lane writes tanh.
//
// ROUND-13 FIX: the xp prefetch is now a distance-4 named-register pipeline.
// Previous rounds rotated one register chain (nxa=nxb; nxb=nxc; nxc=LDG),
// making the LDG's destination register be READ one iteration after issue —
// an effective prefetch distance of ONE step (~200cy) against a ~600-900cy
// DRAM/L2 latency. That exposed latency was the invariant ~1000cy/step wall
// across rounds 4-12. Here loads for steps t+4..t+7 are issued (MLP=4)
// before executing steps t..t+3, and their registers are only read 4 steps
// (~1000+cy) later.
// ---------------------------------------------------------------------------
__global__ __launch_bounds__(256, 2) void rnn_scan_kernel(
    const float* __restrict__ Whh, const float* __restrict__ fcw,
    const float* __restrict__ fcb, float* __restrict__ out)
{
    __shared__ __align__(16) float hbuf[2][NH];

    const int tid = threadIdx.x;
    const int j = tid >> 1;
    const int half = tid & 1;
    const int b = blockIdx.x;          // one batch row per CTA

    // weights: 64 contiguous floats W[j][half*64 .. +63] as 32 packed pairs
    u64t w2[32];
    {
        const ulonglong2* wp = (const ulonglong2*)(Whh + j * NH + half * 64);
#pragma unroll
        for (int i = 0; i < 16; i++) {
            ulonglong2 v = wp[i];
            w2[2 * i] = v.x;
            w2[2 * i + 1] = v.y;
        }
    }

    if (tid < NH) hbuf[0][tid] = 0.f;
    __syncthreads();

    const float* __restrict__ xq = g_xp + (long)b * (NT * NH);

    int cur = 0;

    // one RNN step given this thread's xp value for the step
    auto do_step = [&](float xv) {
        const float* hs = &hbuf[cur][half * 64];
        u64t ca = 0ull, cb = 0ull;
#pragma unroll
        for (int i = 0; i < 4; i++) {
            ulonglong2 p = *(const ulonglong2*)(hs + i * 16);
            ulonglong2 q = *(const ulonglong2*)(hs + i * 16 + 4);
            ulonglong2 r = *(const ulonglong2*)(hs + i * 16 + 8);
            ulonglong2 s = *(const ulonglong2*)(hs + i * 16 + 12);
            ffma2(ca, p.x, w2[i * 8 + 0]);
            ffma2(cb, p.y, w2[i * 8 + 1]);
            ffma2(ca, q.x, w2[i * 8 + 2]);
            ffma2(cb, q.y, w2[i * 8 + 3]);
            ffma2(ca, r.x, w2[i * 8 + 4]);
            ffma2(cb, r.y, w2[i * 8 + 5]);
            ffma2(ca, s.x, w2[i * 8 + 6]);
            ffma2(cb, s.y, w2[i * 8 + 7]);
        }
        float lo, hi;
        unpack2(ca, lo, hi); float sum = lo + hi;
        unpack2(cb, lo, hi); sum += lo + hi;
        float tot = sum + __shfl_xor_sync(0xffffffffu, sum, 1);
        int nxt = cur ^ 1;
        if (half == 0) hbuf[nxt][j] = tanh_fast(tot + xv);
        __syncthreads();
        cur = nxt;
    };

    // distance-4 prefetch pipeline (g_xp padded -> tail loads safe)
    float pf0 = xq[0 * NH + j];
    float pf1 = xq[1 * NH + j];
    float pf2 = xq[2 * NH + j];
    float pf3 = xq[3 * NH + j];

    for (int tb = 0; tb < NT; tb += 4) {
        // issue next block's loads first: regs n0..n3 read 4 steps from now
        float n0 = __ldg(&xq[(tb + 4) * NH + j]);
        float n1 = __ldg(&xq[(tb + 5) * NH + j]);
        float n2 = __ldg(&xq[(tb + 6) * NH + j]);
        float n3 = __ldg(&xq[(tb + 7) * NH + j]);

        do_step(pf0);
        do_step(pf1);
        do_step(pf2);
        do_step(pf3);

        pf0 = n0; pf1 = n1; pf2 = n2; pf3 = n3;
    }

    // fused FC (128 -> 2): warp 0 -> class 0, warp 1 -> class 1
    if (tid < 64) {
        const int w = tid >> 5, lane = tid & 31;
        const float* h = &hbuf[cur][0];
        float s = 0.f;
#pragma unroll
        for (int kk = 0; kk < NH; kk += 32)
            s += h[kk + lane] * fcw[w * NH + kk + lane];
#pragma unroll
        for (int off = 16; off > 0; off >>= 1)
            s += __shfl_xor_sync(0xffffffffu, s, off);
        if (lane == 0) out[b * 2 + w] = s + fcb[w];
    }
}

// ---------------------------------------------------------------------------
extern "C" void kernel_launch(void* const* d_in, const int* in_sizes, int n_in,
                              void* d_out, int out_size)
{
    const float* x   = (const float*)d_in[0];
    const float* Wih = (const float*)d_in[1];
    const float* Whh = (const float*)d_in[2];
    const float* bih = (const float*)d_in[3];
    const float* bhh = (const float*)d_in[4];
    const float* fcw = (const float*)d_in[5];
    const float* fcb = (const float*)d_in[6];
    float* out = (float*)d_out;

    (void)in_sizes; (void)n_in; (void)out_size;

    gemm_xp_kernel<<<(NB * NT) / BM, 256>>>(x, Wih, bih, bhh);
    rnn_scan_kernel<<<NB, 256>>>(Whh, fcw, fcb, out);
}

// round 14
// speedup vs baseline: 2.1080x; 1.1814x over previous
#include <cuda_runtime.h>
#include <cstdint>

#define NB 256
#define NT 512
#define NI 300
#define NH 128

typedef unsigned long long u64t;

// Precomputed input projections xp[b][t][h], padded by 8 timesteps so the
// distance-4 register prefetch in the scan can overrun harmlessly.
__device__ float g_xp[(NB * NT + 8) * NH];

// ---------------- packed f32x2 helpers (sm_103a) ----------------
__device__ __forceinline__ u64t pack2(float lo, float hi) {
    u64t r;
    asm("mov.b64 %0, {%1, %2};" : "=l"(r) : "f"(lo), "f"(hi));
    return r;
}
__device__ __forceinline__ void unpack2(u64t v, float& lo, float& hi) {
    asm("mov.b64 {%0, %1}, %2;" : "=f"(lo), "=f"(hi) : "l"(v));
}
__device__ __forceinline__ void ffma2(u64t& d, u64t a, u64t b) {
    asm("fma.rn.f32x2 %0, %1, %2, %0;" : "+l"(d) : "l"(a), "l"(b));
}
__device__ __forceinline__ void cp_async4(uint32_t s, const void* g) {
    asm volatile("cp.async.ca.shared.global [%0], [%1], 4;" :: "r"(s), "l"(g));
}
// fast tanh: 1 - 2/(e^{2x}+1) via MUFU ex2 + rcp (~1e-6 abs err)
__device__ __forceinline__ float tanh_fast(float x) {
    float e;
    asm("ex2.approx.f32 %0, %1;" : "=f"(e) : "f"(x * 2.885390082f));  // 2*log2(e)
    float r;
    asm("rcp.approx.f32 %0, %1;" : "=f"(r) : "f"(e + 1.0f));
    return fmaf(-2.0f, r, 1.0f);
}

// ---------------------------------------------------------------------------
// Phase 1: xp = x @ W_ih^T + (b_ih + b_hh)   — ROUND-6 VERSION (known good)
// ---------------------------------------------------------------------------
#define BM 128
#define BN 128
#define BK 20
#define BMP (BM + 4)
#define NTILES (NI / BK)

__global__ __launch_bounds__(256, 2) void gemm_xp_kernel(
    const float* __restrict__ x, const float* __restrict__ Wih,
    const float* __restrict__ bih, const float* __restrict__ bhh)
{
    __shared__ __align__(16) float xs[2][BK][BMP];
    __shared__ __align__(16) float ws[2][BK][BMP];
    __shared__ float bias_s[NH];

    const int tid = threadIdx.x;
    const int m0 = blockIdx.x * BM;
    if (tid < NH) bias_s[tid] = bih[tid] + bhh[tid];

    const int tr = tid >> 4;
    const int tc = tid & 15;

    uint32_t offS[10];
    int offG[10];
#pragma unroll
    for (int it = 0; it < 10; it++) {
        int idx = tid + it * 256;
        int r = idx / BK, kk = idx % BK;
        offS[it] = (uint32_t)(kk * BMP + r) * 4u;
        offG[it] = r * NI + kk;
    }

    const uint32_t xsb0 = (uint32_t)__cvta_generic_to_shared(&xs[0][0][0]);
    const uint32_t xsb1 = (uint32_t)__cvta_generic_to_shared(&xs[1][0][0]);
    const uint32_t wsb0 = (uint32_t)__cvta_generic_to_shared(&ws[0][0][0]);
    const uint32_t wsb1 = (uint32_t)__cvta_generic_to_shared(&ws[1][0][0]);

    const float* xg = x + (long)m0 * NI;

    u64t acc2[8][4];
#pragma unroll
    for (int i = 0; i < 8; i++)
#pragma unroll
        for (int p = 0; p < 4; p++) acc2[i][p] = 0ull;

#define ISSUE_TILE(tile, xsb, wsb)                                   \
    do {                                                             \
        const float* xt_ = xg + (tile) * BK;                         \
        const float* wt_ = Wih + (tile) * BK;                        \
        _Pragma("unroll")                                            \
        for (int it = 0; it < 10; it++) {                            \
            cp_async4((xsb) + offS[it], xt_ + offG[it]);             \
            cp_async4((wsb) + offS[it], wt_ + offG[it]);             \
        }                                                            \
        asm volatile("cp.async.commit_group;");                      \
    } while (0)

    ISSUE_TILE(0, xsb0, wsb0);

    for (int tile = 0; tile < NTILES; tile++) {
        int buf = tile & 1;
        if (tile + 1 < NTILES) {
            if (buf == 0) ISSUE_TILE(tile + 1, xsb1, wsb1);
            else          ISSUE_TILE(tile + 1, xsb0, wsb0);
            asm volatile("cp.async.wait_group 1;");
        } else {
            asm volatile("cp.async.wait_group 0;");
        }
        __syncthreads();

        const float(*xsp)[BMP] = xs[buf];
        const float(*wsp)[BMP] = ws[buf];
#pragma unroll 4
        for (int kk = 0; kk < BK; kk++) {
            float4 a0 = *(const float4*)&xsp[kk][tr * 8];
            float4 a1 = *(const float4*)&xsp[kk][tr * 8 + 4];
            ulonglong2 bq0 = *(const ulonglong2*)&wsp[kk][tc * 8];
            ulonglong2 bq1 = *(const ulonglong2*)&wsp[kk][tc * 8 + 4];
            u64t bp[4] = {bq0.x, bq0.y, bq1.x, bq1.y};
            float av[8] = {a0.x, a0.y, a0.z, a0.w, a1.x, a1.y, a1.z, a1.w};
#pragma unroll
            for (int i = 0; i < 8; i++) {
                u64t ap = pack2(av[i], av[i]);
#pragma unroll
                for (int p = 0; p < 4; p++)
                    ffma2(acc2[i][p], ap, bp[p]);
            }
        }
        __syncthreads();
    }
#undef ISSUE_TILE

#pragma unroll
    for (int i = 0; i < 8; i++) {
        int r = m0 + tr * 8 + i;
        float* pdst = &g_xp[r * NH + tc * 8];
#pragma unroll
        for (int p = 0; p < 4; p++) {
            float lo, hi;
            unpack2(acc2[i][p], lo, hi);
            float2 v;
            v.x = lo + bias_s[tc * 8 + 2 * p];
            v.y = hi + bias_s[tc * 8 + 2 * p + 1];
            *(float2*)(pdst + 2 * p) = v;
        }
    }
}

// ---------------------------------------------------------------------------
// Phase 2: scan. ONE batch row per CTA, 256 CTAs x 256 threads, 2 CTAs/SM.
//
// ROUND-14: the rounds-4..13 invariant (~1000cy/step) was LDS BYTE volume:
// 16 LDS.128/thread/step at 512B/warp-instr through a 128B/cy crossbar.
// New layout: thread (og = tid>>4, kg = tid&15) computes EIGHT outputs
// j = og*8..+7 over an 8-wide k-slice k = kg*8..+7:
//   - 2 LDS.128 per thread per step (8x fewer bytes), conflict-free
//   - 32 FFMA2 (8 chains of 4)
//   - 4-stage butterfly over the 16 kg-lanes (masks 8,4,2,1): 8 SHFL,
//     value-ternaries only (static array indices -> no local-mem spills)
//   - lane ends owning j = og*8 + 4*b8 + 2*b4 + b2 (dup over kg&1);
//     kg&1==0 lane applies tanh_fast and writes
//   - xp via distance-4 named-register prefetch (round-13 fix kept)
// ---------------------------------------------------------------------------
__global__ __launch_bounds__(256, 2) void rnn_scan_kernel(
    const float* __restrict__ Whh, const float* __restrict__ fcw,
    const float* __restrict__ fcb, float* __restrict__ out)
{
    __shared__ __align__(16) float hbuf[2][NH];

    const int tid = threadIdx.x;
    const int og = tid >> 4;        // 0..15: outputs og*8 .. +7
    const int kg = tid & 15;        // 0..15: k-slice kg*8 .. +7
    const int b = blockIdx.x;

    const bool b8 = (kg & 8) != 0;
    const bool b4 = (kg & 4) != 0;
    const bool b2 = (kg & 2) != 0;
    const bool writer = (kg & 1) == 0;
    const int jmine = og * 8 + (b8 ? 4 : 0) + (b4 ? 2 : 0) + (b2 ? 1 : 0);

    // weights: w2[jl][i] = {W[og*8+jl][kg*8+2i], W[og*8+jl][kg*8+2i+1]}
    u64t w2[8][4];
#pragma unroll
    for (int jl = 0; jl < 8; jl++) {
        const ulonglong2* wp =
            (const ulonglong2*)(Whh + (og * 8 + jl) * NH + kg * 8);
        ulonglong2 v0 = wp[0], v1 = wp[1];
        w2[jl][0] = v0.x; w2[jl][1] = v0.y;
        w2[jl][2] = v1.x; w2[jl][3] = v1.y;
    }

    if (tid < NH) hbuf[0][tid] = 0.f;
    __syncthreads();

    const float* __restrict__ xq = g_xp + (long)b * (NT * NH);

    int cur = 0;

    auto do_step = [&](float xv) {
        const float* hs = &hbuf[cur][kg * 8];
        ulonglong2 hv0 = *(const ulonglong2*)(hs);
        ulonglong2 hv1 = *(const ulonglong2*)(hs + 4);
        u64t hp0 = hv0.x, hp1 = hv0.y, hp2 = hv1.x, hp3 = hv1.y;

        u64t c[8];
#pragma unroll
        for (int jl = 0; jl < 8; jl++) c[jl] = 0ull;
#pragma unroll
        for (int jl = 0; jl < 8; jl++) {
            ffma2(c[jl], hp0, w2[jl][0]);
            ffma2(c[jl], hp1, w2[jl][1]);
            ffma2(c[jl], hp2, w2[jl][2]);
            ffma2(c[jl], hp3, w2[jl][3]);
        }

        float s[8];
#pragma unroll
        for (int jl = 0; jl < 8; jl++) {
            float lo, hi;
            unpack2(c[jl], lo, hi);
            s[jl] = lo + hi;
        }

        // stage 1 (xor 8): 8 -> 4 ; keep lower half if b8==0
        float t1[4];
#pragma unroll
        for (int i = 0; i < 4; i++) {
            float keep = b8 ? s[4 + i] : s[i];
            float send = b8 ? s[i] : s[4 + i];
            t1[i] = keep + __shfl_xor_sync(0xffffffffu, send, 8);
        }
        // stage 2 (xor 4): 4 -> 2
        float t2[2];
#pragma unroll
        for (int i = 0; i < 2; i++) {
            float keep = b4 ? t1[2 + i] : t1[i];
            float send = b4 ? t1[i] : t1[2 + i];
            t2[i] = keep + __shfl_xor_sync(0xffffffffu, send, 4);
        }
        // stage 3 (xor 2): 2 -> 1
        float keep3 = b2 ? t2[1] : t2[0];
        float send3 = b2 ? t2[0] : t2[1];
        float t3 = keep3 + __shfl_xor_sync(0xffffffffu, send3, 2);
        // stage 4 (xor 1): both lanes same output -> plain sum
        float tot = t3 + __shfl_xor_sync(0xffffffffu, t3, 1);

        int nxt = cur ^ 1;
        if (writer) hbuf[nxt][jmine] = tanh_fast(tot + xv);
        __syncthreads();
        cur = nxt;
    };

    // distance-4 prefetch pipeline (g_xp padded -> tail loads safe)
    float pf0 = xq[0 * NH + jmine];
    float pf1 = xq[1 * NH + jmine];
    float pf2 = xq[2 * NH + jmine];
    float pf3 = xq[3 * NH + jmine];

    for (int tb = 0; tb < NT; tb += 4) {
        float n0 = __ldg(&xq[(tb + 4) * NH + jmine]);
        float n1 = __ldg(&xq[(tb + 5) * NH + jmine]);
        float n2 = __ldg(&xq[(tb + 6) * NH + jmine]);
        float n3 = __ldg(&xq[(tb + 7) * NH + jmine]);

        do_step(pf0);
        do_step(pf1);
        do_step(pf2);
        do_step(pf3);

        pf0 = n0; pf1 = n1; pf2 = n2; pf3 = n3;
    }

    // fused FC (128 -> 2): warp 0 -> class 0, warp 1 -> class 1
    if (tid < 64) {
        const int w = tid >> 5, lane = tid & 31;
        const float* h = &hbuf[cur][0];
        float s = 0.f;
#pragma unroll
        for (int kk = 0; kk < NH; kk += 32)
            s += h[kk + lane] * fcw[w * NH + kk + lane];
#pragma unroll
        for (int off = 16; off > 0; off >>= 1)
            s += __shfl_xor_sync(0xffffffffu, s, off);
        if (lane == 0) out[b * 2 + w] = s + fcb[w];
    }
}

// ---------------------------------------------------------------------------
extern "C" void kernel_launch(void* const* d_in, const int* in_sizes, int n_in,
                              void* d_out, int out_size)
{
    const float* x   = (const float*)d_in[0];
    const float* Wih = (const float*)d_in[1];
    const float* Whh = (const float*)d_in[2];
    const float* bih = (const float*)d_in[3];
    const float* bhh = (const float*)d_in[4];
    const float* fcw = (const float*)d_in[5];
    const float* fcb = (const float*)d_in[6];
    float* out = (float*)d_out;

    (void)in_sizes; (void)n_in; (void)out_size;

    gemm_xp_kernel<<<(NB * NT) / BM, 256>>>(x, Wih, bih, bhh);
    rnn_scan_kernel<<<NB, 256>>>(Whh, fcw, fcb, out);
}